// round 5
// baseline (speedup 1.0000x reference)
#include <cuda_runtime.h>
#include <cstdint>

#define B_DIM 8
#define C_DIM 4
#define T_DIM 262144
#define T4 (T_DIM / 4)

#define NTHREADS 256
#define BLK_PER_BATCH 32
#define NBLOCKS (BLK_PER_BATCH * B_DIM)          // 256 blocks: one full wave
#define TILES_PER_BLOCK 8
#define COLS_PER_TILE 256                        // float4 columns per stage
#define NSTREAMS 8                               // x0..x3, y0..y3
#define STREAM_STAGE_BYTES (COLS_PER_TILE * 16)  // 4096
#define STAGE_BYTES (NSTREAMS * STREAM_STAGE_BYTES)  // 32768
#define NSTAGES 2
#define SMEM_BYTES (NSTAGES * STAGE_BYTES)       // 65536

// Scratch (zero-init at load; last block resets -> clean state for every replay)
__device__ float g_partial[B_DIM][16];
__device__ unsigned int g_ticket;

__device__ __forceinline__ uint32_t smem_u32(const void* p) {
    uint32_t a;
    asm("{ .reg .u64 t; cvta.to.shared.u64 t, %1; cvt.u32.u64 %0, t; }"
        : "=r"(a) : "l"(p));
    return a;
}
__device__ __forceinline__ void cp_async16(uint32_t dst, const void* src) {
    asm volatile("cp.async.cg.shared.global [%0], [%1], 16;"
                 :: "r"(dst), "l"(src) : "memory");
}
__device__ __forceinline__ void cp_commit() {
    asm volatile("cp.async.commit_group;" ::: "memory");
}
__device__ __forceinline__ void cp_wait1() {
    asm volatile("cp.async.wait_group 1;" ::: "memory");
}
__device__ __forceinline__ void cp_wait0() {
    asm volatile("cp.async.wait_group 0;" ::: "memory");
}

__global__ void __launch_bounds__(NTHREADS) pit_cpasync_kernel(
    const float* __restrict__ x, const float* __restrict__ y,
    float* __restrict__ out) {
    extern __shared__ char smem[];
    __shared__ float s_acc[16];
    __shared__ float s_d[B_DIM * 16];
    __shared__ bool s_is_last;

    const int tid = threadIdx.x;
    const int b = blockIdx.y;
    const int blk = blockIdx.x;

    const uint32_t smem_base = smem_u32(smem);

    // Per-stream global base pointers (bytes): x ch 0..3, then y ch 0..3
    const char* sbase[NSTREAMS];
    {
        const char* xb = (const char*)(x + (long long)b * C_DIM * T_DIM);
        const char* yb = (const char*)(y + (long long)b * C_DIM * T_DIM);
#pragma unroll
        for (int c = 0; c < C_DIM; c++) {
            sbase[c] = xb + (long long)c * T_DIM * 4;
            sbase[4 + c] = yb + (long long)c * T_DIM * 4;
        }
    }

    // Issue one 32 KB stage: each thread copies one 16B chunk per stream.
    auto issue = [&](int k) {
        const int s = k & (NSTAGES - 1);
        const long long goff =
            ((long long)(blk * TILES_PER_BLOCK + k) * COLS_PER_TILE + tid) * 16;
        const uint32_t dst = smem_base + s * STAGE_BYTES + tid * 16;
#pragma unroll
        for (int str = 0; str < NSTREAMS; str++)
            cp_async16(dst + str * STREAM_STAGE_BYTES, sbase[str] + goff);
        cp_commit();
    };

    issue(0);

    float acc[16];
#pragma unroll
    for (int k = 0; k < 16; k++) acc[k] = 0.0f;

    for (int k = 0; k < TILES_PER_BLOCK; k++) {
        if (k + 1 < TILES_PER_BLOCK) {
            issue(k + 1);   // writes the other buffer (safe: barrier at loop tail)
            cp_wait1();     // current stage (group k) complete
        } else {
            cp_wait0();
        }
        __syncthreads();    // all threads' copies for this stage visible

        const char* stage = smem + (k & (NSTAGES - 1)) * STAGE_BYTES + tid * 16;
        float4 xv0 = *(const float4*)(stage + 0 * STREAM_STAGE_BYTES);
        float4 xv1 = *(const float4*)(stage + 1 * STREAM_STAGE_BYTES);
        float4 xv2 = *(const float4*)(stage + 2 * STREAM_STAGE_BYTES);
        float4 xv3 = *(const float4*)(stage + 3 * STREAM_STAGE_BYTES);
#pragma unroll
        for (int i = 0; i < C_DIM; i++) {
            const float4 yv = *(const float4*)(stage + (4 + i) * STREAM_STAGE_BYTES);
            float d;
            d = xv0.x - yv.x; acc[i*4+0] += d*d;  d = xv0.y - yv.y; acc[i*4+0] += d*d;
            d = xv0.z - yv.z; acc[i*4+0] += d*d;  d = xv0.w - yv.w; acc[i*4+0] += d*d;
            d = xv1.x - yv.x; acc[i*4+1] += d*d;  d = xv1.y - yv.y; acc[i*4+1] += d*d;
            d = xv1.z - yv.z; acc[i*4+1] += d*d;  d = xv1.w - yv.w; acc[i*4+1] += d*d;
            d = xv2.x - yv.x; acc[i*4+2] += d*d;  d = xv2.y - yv.y; acc[i*4+2] += d*d;
            d = xv2.z - yv.z; acc[i*4+2] += d*d;  d = xv2.w - yv.w; acc[i*4+2] += d*d;
            d = xv3.x - yv.x; acc[i*4+3] += d*d;  d = xv3.y - yv.y; acc[i*4+3] += d*d;
            d = xv3.z - yv.z; acc[i*4+3] += d*d;  d = xv3.w - yv.w; acc[i*4+3] += d*d;
        }
        __syncthreads();    // done reading this buffer before it's re-issued
    }

    // ---- block reduction ----
#pragma unroll
    for (int kk = 0; kk < 16; kk++) {
#pragma unroll
        for (int off = 16; off > 0; off >>= 1)
            acc[kk] += __shfl_down_sync(0xffffffff, acc[kk], off);
    }
    if (tid < 16) s_acc[tid] = 0.0f;
    __syncthreads();
    if ((tid & 31) == 0) {
#pragma unroll
        for (int kk = 0; kk < 16; kk++) atomicAdd(&s_acc[kk], acc[kk]);
    }
    __syncthreads();
    if (tid < 16) atomicAdd(&g_partial[b][tid], s_acc[tid]);

    // ---- last-block-done finalize ----
    __threadfence();
    if (tid == 0) {
        unsigned int t = atomicAdd(&g_ticket, 1u);
        s_is_last = (t == NBLOCKS - 1);
    }
    __syncthreads();
    if (!s_is_last) return;

    if (tid < B_DIM * 16)
        s_d[tid] = __ldcg(&((const float*)g_partial)[tid]);
    __syncthreads();

    if (tid == 0) {
        const float inv_t = 1.0f / (float)T_DIM;
        float total = 0.0f;
        for (int bb = 0; bb < B_DIM; bb++) {
            const float* d = &s_d[bb * 16];
            float best = 3.4e38f;
            for (int p0 = 0; p0 < 4; p0++)
                for (int p1 = 0; p1 < 4; p1++) {
                    if (p1 == p0) continue;
                    for (int p2 = 0; p2 < 4; p2++) {
                        if (p2 == p0 || p2 == p1) continue;
                        int p3 = 6 - p0 - p1 - p2;
                        float c = d[0 * 4 + p0] + d[1 * 4 + p1] +
                                  d[2 * 4 + p2] + d[3 * 4 + p3];
                        best = fminf(best, c);
                    }
                }
            total += best * inv_t;
        }
        out[0] = total;
        g_ticket = 0;
    }
    if (tid < B_DIM * 16)
        ((float*)g_partial)[tid] = 0.0f;
}

extern "C" void kernel_launch(void* const* d_in, const int* in_sizes, int n_in,
                              void* d_out, int out_size) {
    const float* x = (const float*)d_in[0];
    const float* y = (const float*)d_in[1];
    float* out = (float*)d_out;

    cudaFuncSetAttribute(pit_cpasync_kernel,
                         cudaFuncAttributeMaxDynamicSharedMemorySize, SMEM_BYTES);
    dim3 grid(BLK_PER_BATCH, B_DIM);
    pit_cpasync_kernel<<<grid, NTHREADS, SMEM_BYTES>>>(x, y, out);
}

// round 6
// speedup vs baseline: 1.5000x; 1.5000x over previous
#include <cuda_runtime.h>
#include <cstdint>

#define B_DIM 8
#define C_DIM 4
#define T_DIM 262144
#define T4 (T_DIM / 4)

#define NTHREADS 128
#define BLK_PER_BATCH 64
#define NBLOCKS (BLK_PER_BATCH * B_DIM)    // 512
#define ITERS 8                            // 64 blk * 128 thr * 8 = 65536 = T4

typedef unsigned long long u64;

// Scratch (zero-init at load; last block resets -> clean state each replay)
__device__ float g_partial[B_DIM][16];
__device__ unsigned int g_ticket;

__device__ __forceinline__ u64 ffma2(u64 a, u64 b, u64 c) {
    u64 d;
    asm("fma.rn.f32x2 %0, %1, %2, %3;" : "=l"(d) : "l"(a), "l"(b), "l"(c));
    return d;
}

__global__ void __launch_bounds__(NTHREADS) pit_f32x2_kernel(
    const float* __restrict__ x, const float* __restrict__ y,
    float* __restrict__ out) {
    const int tid = threadIdx.x;
    const int b = blockIdx.y;

    const ulonglong2* __restrict__ x2 =
        (const ulonglong2*)(x + (long long)b * C_DIM * T_DIM);
    const ulonglong2* __restrict__ y2 =
        (const ulonglong2*)(y + (long long)b * C_DIM * T_DIM);

    const u64 NEG1 = 0xBF800000BF800000ULL;  // packed (-1.0f, -1.0f)

    u64 acc[16];
#pragma unroll
    for (int k = 0; k < 16; k++) acc[k] = 0ULL;

    const int base = blockIdx.x * (NTHREADS * ITERS) + tid;
#pragma unroll 2
    for (int it = 0; it < ITERS; it++) {
        const int col = base + it * NTHREADS;
        ulonglong2 xv[C_DIM], yv[C_DIM];
#pragma unroll
        for (int c = 0; c < C_DIM; c++) {
            xv[c] = x2[c * (T4 / 1) + col];   // T4 ulonglong2 per channel
            yv[c] = y2[c * (T4 / 1) + col];
        }
#pragma unroll
        for (int i = 0; i < C_DIM; i++) {
#pragma unroll
            for (int j = 0; j < C_DIM; j++) {
                u64 dlo = ffma2(yv[i].x, NEG1, xv[j].x);   // x - y (exact)
                u64 dhi = ffma2(yv[i].y, NEG1, xv[j].y);
                acc[i * 4 + j] = ffma2(dlo, dlo, acc[i * 4 + j]);
                acc[i * 4 + j] = ffma2(dhi, dhi, acc[i * 4 + j]);
            }
        }
    }

    // Unpack f32x2 accumulators -> scalar
    float sacc[16];
#pragma unroll
    for (int k = 0; k < 16; k++) {
        float lo = __uint_as_float((unsigned)(acc[k] & 0xFFFFFFFFULL));
        float hi = __uint_as_float((unsigned)(acc[k] >> 32));
        sacc[k] = lo + hi;
    }

    // Warp reduction
#pragma unroll
    for (int k = 0; k < 16; k++) {
#pragma unroll
        for (int off = 16; off > 0; off >>= 1)
            sacc[k] += __shfl_down_sync(0xffffffff, sacc[k], off);
    }

    __shared__ float s_acc[16];
    __shared__ float s_d[B_DIM * 16];
    __shared__ bool s_is_last;

    if (tid < 16) s_acc[tid] = 0.0f;
    __syncthreads();
    if ((tid & 31) == 0) {
#pragma unroll
        for (int k = 0; k < 16; k++) atomicAdd(&s_acc[k], sacc[k]);
    }
    __syncthreads();
    if (tid < 16) atomicAdd(&g_partial[b][tid], s_acc[tid]);

    // ---- last-block-done finalize ----
    __threadfence();
    if (tid == 0) {
        unsigned int t = atomicAdd(&g_ticket, 1u);
        s_is_last = (t == NBLOCKS - 1);
    }
    __syncthreads();
    if (!s_is_last) return;

    if (tid < B_DIM * 16)
        s_d[tid] = __ldcg(&((const float*)g_partial)[tid]);
    __syncthreads();

    if (tid == 0) {
        const float inv_t = 1.0f / (float)T_DIM;
        float total = 0.0f;
        for (int bb = 0; bb < B_DIM; bb++) {
            const float* d = &s_d[bb * 16];
            float best = 3.4e38f;
            for (int p0 = 0; p0 < 4; p0++)
                for (int p1 = 0; p1 < 4; p1++) {
                    if (p1 == p0) continue;
                    for (int p2 = 0; p2 < 4; p2++) {
                        if (p2 == p0 || p2 == p1) continue;
                        int p3 = 6 - p0 - p1 - p2;
                        float c = d[0 * 4 + p0] + d[1 * 4 + p1] +
                                  d[2 * 4 + p2] + d[3 * 4 + p3];
                        best = fminf(best, c);
                    }
                }
            total += best * inv_t;
        }
        out[0] = total;
        g_ticket = 0;
    }
    if (tid < B_DIM * 16)
        ((float*)g_partial)[tid] = 0.0f;
}

extern "C" void kernel_launch(void* const* d_in, const int* in_sizes, int n_in,
                              void* d_out, int out_size) {
    const float* x = (const float*)d_in[0];
    const float* y = (const float*)d_in[1];
    float* out = (float*)d_out;

    dim3 grid(BLK_PER_BATCH, B_DIM);
    pit_f32x2_kernel<<<grid, NTHREADS>>>(x, y, out);
}